// round 16
// baseline (speedup 1.0000x reference)
#include <cuda_runtime.h>
#include <cuda_fp16.h>
#include <math.h>

// Problem constants
#define B_    2
#define S_    1024
#define HID_  2048
#define HQ_   32
#define HKV_  8
#define HD_   64
#define MTOK  (B_ * S_)

// Scratch (half, all natural layouts)
__device__ __half g_q[MTOK * HID_];
__device__ __half g_k[MTOK * 512];
__device__ __half g_v[MTOK * 512];
__device__ __half g_attn[MTOK * HID_];
__device__ __half g_rh[MTOK * HID_];
__device__ __half g_wq[HID_ * HID_];
__device__ __half g_wk[HID_ * 512];
__device__ __half g_wv[HID_ * 512];
__device__ __half g_wo[HID_ * HID_];

#define MMA_F16(D, A, B0, B1)                                               \
    asm volatile(                                                           \
        "mma.sync.aligned.m16n8k16.row.col.f32.f16.f16.f32 "                \
        "{%0,%1,%2,%3}, {%4,%5,%6,%7}, {%8,%9}, {%0,%1,%2,%3};"             \
        : "+f"((D)[0]), "+f"((D)[1]), "+f"((D)[2]), "+f"((D)[3])            \
        : "r"((A)[0]), "r"((A)[1]), "r"((A)[2]), "r"((A)[3]),               \
          "r"(B0), "r"(B1))

#define LDSM4(R0, R1, R2, R3, ADDR)                                         \
    asm volatile("ldmatrix.sync.aligned.m8n8.x4.shared.b16 {%0,%1,%2,%3}, [%4];" \
        : "=r"(R0), "=r"(R1), "=r"(R2), "=r"(R3) : "r"(ADDR))

#define LDSM4T(R0, R1, R2, R3, ADDR)                                        \
    asm volatile("ldmatrix.sync.aligned.m8n8.x4.trans.shared.b16 {%0,%1,%2,%3}, [%4];" \
        : "=r"(R0), "=r"(R1), "=r"(R2), "=r"(R3) : "r"(ADDR))

#define CPA16(smu32, gptr) \
    asm volatile("cp.async.cg.shared.global [%0], [%1], 16;" :: "r"(smu32), "l"(gptr))
#define CPA_COMMIT() asm volatile("cp.async.commit_group;")
#define CPA_WAIT0()  asm volatile("cp.async.wait_group 0;" ::: "memory")
#define CPA_WAIT1()  asm volatile("cp.async.wait_group 1;" ::: "memory")

__device__ __forceinline__ unsigned packh2(float lo, float hi) {
    __half2 h = __floats2half2_rn(lo, hi);
    return *(unsigned*)&h;
}

// ---------------------------------------------------------------------------
// Convert pre-pass: pure elementwise fp32 -> fp16 (all natural layouts).
// Units: float4. hid 1M | Wq 1M | Wk .25M | Wv .25M | Wo 1M
// ---------------------------------------------------------------------------
#define CSEG0 (MTOK * HID_ / 4)
#define CSEG1 (CSEG0 + HID_ * HID_ / 4)
#define CSEG2 (CSEG1 + HID_ * 512 / 4)
#define CSEG3 (CSEG2 + HID_ * 512 / 4)
#define CSEG4 (CSEG3 + HID_ * HID_ / 4)

__global__ void convert_all_kernel(const float* __restrict__ hid,
                                   const float* __restrict__ Wq,
                                   const float* __restrict__ Wk,
                                   const float* __restrict__ Wv,
                                   const float* __restrict__ Wo)
{
    int i = blockIdx.x * blockDim.x + threadIdx.x;
    if (i >= CSEG4) return;
    const float4* src; uint2* dst; int j;
    if (i < CSEG0)      { src = (const float4*)hid; dst = (uint2*)g_rh; j = i; }
    else if (i < CSEG1) { src = (const float4*)Wq;  dst = (uint2*)g_wq; j = i - CSEG0; }
    else if (i < CSEG2) { src = (const float4*)Wk;  dst = (uint2*)g_wk; j = i - CSEG1; }
    else if (i < CSEG3) { src = (const float4*)Wv;  dst = (uint2*)g_wv; j = i - CSEG2; }
    else                { src = (const float4*)Wo;  dst = (uint2*)g_wo; j = i - CSEG3; }
    float4 v = src[j];
    dst[j] = make_uint2(packh2(v.x, v.y), packh2(v.z, v.w));
}

// ---------------------------------------------------------------------------
// fp16 pipelined GEMM with ldmatrix fragments.
// A half [M][2048] natural; B half [K][N] natural (k-major).
// CTA 128x128x32, 128 thr (4 warps 2x2), warp tile 64x64, 3-stage cp.async.
// Smem: A [128 m][40 halfs] (80B rows), B [32 k][136 halfs] (272B rows).
// A-frags: ldmatrix.x4; B-frags: ldmatrix.x4.trans. Both conflict-free.
// ---------------------------------------------------------------------------
#define GSTG   3
#define AROWB  80
#define BROWB  272
#define AS_B   (128 * AROWB)
#define BS_B   (32 * BROWB)
#define STG_B  (AS_B + BS_B)
#define GEMM_SMEM (GSTG * STG_B)
#define NKT    (HID_ / 32)

__global__ __launch_bounds__(128, 2)
void gemm_f16(const __half* __restrict__ A,
              const __half* __restrict__ Bq, const __half* __restrict__ Bk,
              const __half* __restrict__ Bv,
              __half* __restrict__ Cq, __half* __restrict__ Ck,
              __half* __restrict__ Cv, float* __restrict__ Cf, int outmode)
{
    extern __shared__ char smg[];
    const unsigned smb = (unsigned)__cvta_generic_to_shared(smg);

    const int bx = blockIdx.x;
    const int by = blockIdx.y;

    const __half* Bp; int Nb, n0;
    __half* Ch = 0; float* Cfo = 0;
    if (outmode == 1) { Bp = Bq; Cfo = Cf; Nb = 2048; n0 = bx * 128; }
    else if (bx < 16) { Bp = Bq; Ch = Cq; Nb = 2048; n0 = bx * 128; }
    else if (bx < 20) { Bp = Bk; Ch = Ck; Nb = 512;  n0 = (bx - 16) * 128; }
    else              { Bp = Bv; Ch = Cv; Nb = 512;  n0 = (bx - 20) * 128; }

    const int tid  = threadIdx.x;
    const int wid  = tid >> 5;
    const int lane = tid & 31;
    const int wm   = wid >> 1;
    const int wn   = wid & 1;
    const int g    = lane >> 2;
    const int tg   = lane & 3;
    const int m0   = by * 128;

    const int q_ = lane >> 3, rl = lane & 7;
    // ldmatrix lane offsets (bytes)
    const unsigned a_off = (unsigned)(((q_ & 1) * 8 + rl) * AROWB + (q_ >> 1) * 16);
    const unsigned b_off = (unsigned)(((q_ >> 1) * 8 + rl) * BROWB + (q_ & 1) * 16);

    float acc[4][8][4];
    #pragma unroll
    for (int mi = 0; mi < 4; mi++)
        #pragma unroll
        for (int ni = 0; ni < 8; ni++)
            #pragma unroll
            for (int c = 0; c < 4; c++) acc[mi][ni][c] = 0.f;

    auto load_tile = [&](int kt, int stg) {
        // A: row = tid, 64B (32 halfs)
        {
            const __half* ag = A + (size_t)(m0 + tid) * HID_ + kt * 32;
            unsigned as = smb + stg * STG_B + tid * AROWB;
            #pragma unroll
            for (int j = 0; j < 4; j++)
                CPA16(as + j * 16, (const char*)ag + j * 16);
        }
        // B: 32 rows x 256B -> 512 chunks
        #pragma unroll
        for (int j = 0; j < 4; j++) {
            int c = tid + 128 * j;
            int row = c >> 4, ch = c & 15;
            const __half* bg = Bp + (size_t)(kt * 32 + row) * Nb + n0 + ch * 8;
            CPA16(smb + stg * STG_B + AS_B + row * BROWB + ch * 16, bg);
        }
        CPA_COMMIT();
    };

    load_tile(0, 0);
    load_tile(1, 1);

    for (int kt = 0; kt < NKT; kt++) {
        if (kt < NKT - 1) { CPA_WAIT1(); } else { CPA_WAIT0(); }
        __syncthreads();

        const unsigned aB = smb + (kt % GSTG) * STG_B;
        const unsigned bB = aB + AS_B;

        #pragma unroll
        for (int ks = 0; ks < 2; ks++) {
            unsigned afr[4][4];
            #pragma unroll
            for (int mi = 0; mi < 4; mi++) {
                unsigned ad = aB + (wm * 64 + mi * 16) * AROWB + a_off + 32 * ks;
                LDSM4(afr[mi][0], afr[mi][1], afr[mi][2], afr[mi][3], ad);
            }
            #pragma unroll
            for (int np = 0; np < 4; np++) {
                unsigned r0, r1, r2, r3;
                unsigned bd = bB + 16 * ks * BROWB + b_off
                            + (wn * 64 + np * 16) * 2;
                LDSM4T(r0, r1, r2, r3, bd);
                unsigned bfr0[2] = {r0, r2}, bfr1[2] = {r1, r3};
                #pragma unroll
                for (int mi = 0; mi < 4; mi++) {
                    MMA_F16(acc[mi][2 * np    ], afr[mi], bfr0[0], bfr0[1]);
                    MMA_F16(acc[mi][2 * np + 1], afr[mi], bfr1[0], bfr1[1]);
                }
            }
        }
        __syncthreads();

        if (kt + 2 < NKT) load_tile(kt + 2, (kt + 2) % GSTG);
    }

    #pragma unroll
    for (int mi = 0; mi < 4; mi++) {
        int row0 = m0 + wm * 64 + mi * 16 + g;
        #pragma unroll
        for (int ni = 0; ni < 8; ni++) {
            int col = n0 + wn * 64 + ni * 8 + tg * 2;
            if (outmode == 1) {
                *(float2*)(Cfo + (size_t)row0 * Nb + col) =
                    make_float2(acc[mi][ni][0], acc[mi][ni][1]);
                *(float2*)(Cfo + (size_t)(row0 + 8) * Nb + col) =
                    make_float2(acc[mi][ni][2], acc[mi][ni][3]);
            } else {
                *(unsigned*)(Ch + (size_t)row0 * Nb + col) =
                    packh2(acc[mi][ni][0], acc[mi][ni][1]);
                *(unsigned*)(Ch + (size_t)(row0 + 8) * Nb + col) =
                    packh2(acc[mi][ni][2], acc[mi][ni][3]);
            }
        }
    }
}

// ---------------------------------------------------------------------------
// RoPE (in place on half). X: (MTOK, nheads, 64).
// ---------------------------------------------------------------------------
__global__ void rope_kernel(__half* __restrict__ X,
                            const float* __restrict__ cosT,
                            const float* __restrict__ sinT,
                            int nheads)
{
    int idx = blockIdx.x * blockDim.x + threadIdx.x;
    int total = MTOK * nheads * 32;
    if (idx >= total) return;
    int d  = idx & 31;
    int hh = (idx >> 5) % nheads;
    int t  = idx / (32 * nheads);
    int s  = t & (S_ - 1);

    float c  = __ldg(cosT + s * HD_ + d);
    float sn = __ldg(sinT + s * HD_ + d);

    __half* base = X + ((size_t)t * nheads + hh) * HD_;
    float x0 = __half2float(base[d]);
    float x1 = __half2float(base[d + 32]);
    base[d]      = __float2half_rn(x0 * c - x1 * sn);
    base[d + 32] = __float2half_rn(x1 * c + x0 * sn);
}

// ---------------------------------------------------------------------------
// fp16 flash attention with ldmatrix fragments. 256 thr, 2 q-heads/CTA,
// double-buffered K/V cp.async, P register-resident. All smem tiles natural
// [row][64 halfs] with 144B row stride (conflict-free for ldmatrix).
// K score-frags: ldmatrix.x4; V PV-frags: ldmatrix.x4.trans; Q: ldmatrix.x4.
// qb reversed so long (diagonal) CTAs launch first.
// ---------------------------------------------------------------------------
#define RB   144                      // row stride bytes (64 halfs + 8 pad)
#define OFF_Q0 0
#define OFF_Q1 (64 * RB)
#define OFF_K0 (2 * 64 * RB)
#define OFF_K1 (3 * 64 * RB)
#define OFF_V0 (4 * 64 * RB)
#define OFF_V1 (5 * 64 * RB)
#define ATT_SMEM (6 * 64 * RB)

__global__ __launch_bounds__(256, 2)
void attn_f16(const __half* __restrict__ Q, const __half* __restrict__ K,
              const __half* __restrict__ V, __half* __restrict__ O)
{
    extern __shared__ char smc[];
    const unsigned smb = (unsigned)__cvta_generic_to_shared(smc);

    const int qb   = gridDim.x - 1 - blockIdx.x;   // long CTAs first
    const int hp   = blockIdx.y;
    const int b    = blockIdx.z;
    const int kvh  = hp >> 1;
    const int tid  = threadIdx.x;
    const int wid  = tid >> 5;
    const int lane = tid & 31;
    const int g    = lane >> 2;
    const int tg   = lane & 3;
    const int hsel = wid >> 2;
    const int head = 2 * hp + hsel;
    const int qrow0 = (wid & 3) * 16;

    const int q_ = lane >> 3, rl = lane & 7;
    const unsigned nt_off = (unsigned)(((q_ & 1) * 8 + rl) * RB + (q_ >> 1) * 16);
    const unsigned tr_off = (unsigned)(((q_ >> 1) * 8 + rl) * RB + (q_ & 1) * 16);

    const float scale = 0.125f;

    // Prologue: Q (both heads) + K0 + V0
    {
        #pragma unroll
        for (int j = 0; j < 4; j++) {             // Q: 1024 chunks
            int c = tid + j * 256;
            int r = c >> 3, ch = c & 7;
            int hs = r >> 6, qr = r & 63;
            const __half* src = Q + (size_t)(b * S_ + qb * 64 + qr) * HID_
                                + (2 * hp + hs) * HD_ + ch * 8;
            CPA16(smb + (hs ? OFF_Q1 : OFF_Q0) + qr * RB + ch * 16, src);
        }
        #pragma unroll
        for (int j = 0; j < 2; j++) {             // K0
            int c = tid + j * 256;
            int r = c >> 3, ch = c & 7;
            const __half* src = K + (size_t)(b * S_ + r) * 512 + kvh * HD_ + ch * 8;
            CPA16(smb + OFF_K0 + r * RB + ch * 16, src);
        }
        #pragma unroll
        for (int j = 0; j < 2; j++) {             // V0
            int c = tid + j * 256;
            int r = c >> 3, ch = c & 7;
            const __half* src = V + (size_t)(b * S_ + r) * 512 + kvh * HD_ + ch * 8;
            CPA16(smb + OFF_V0 + r * RB + ch * 16, src);
        }
        CPA_COMMIT();
        CPA_WAIT0();
    }
    __syncthreads();

    // Q fragments via ldmatrix.x4 (4 k16 steps over d)
    unsigned qfr[4][4];
    {
        unsigned qB = smb + (hsel ? OFF_Q1 : OFF_Q0) + qrow0 * RB + nt_off;
        #pragma unroll
        for (int kc = 0; kc < 4; kc++)
            LDSM4(qfr[kc][0], qfr[kc][1], qfr[kc][2], qfr[kc][3], qB + 32 * kc);
    }

    float oacc[8][4];
    #pragma unroll
    for (int nt = 0; nt < 8; nt++)
        #pragma unroll
        for (int c = 0; c < 4; c++) oacc[nt][c] = 0.f;
    float m0 = -1e30f, m1 = -1e30f, l0 = 0.f, l1 = 0.f;

    const int qg0 = qb * 64 + qrow0 + g;
    const int qg1 = qg0 + 8;

    for (int kb = 0; kb <= qb; kb++) {
        const int s = kb & 1;
        const unsigned kB = smb + (s ? OFF_K1 : OFF_K0);
        const unsigned vB = smb + (s ? OFF_V1 : OFF_V0);

        if (kb < qb) {
            const int so = s ^ 1;
            #pragma unroll
            for (int j = 0; j < 2; j++) {
                int c = tid + j * 256;
                int r = c >> 3, ch = c & 7;
                const __half* src = K + (size_t)(b * S_ + (kb + 1) * 64 + r) * 512
                                    + kvh * HD_ + ch * 8;
                CPA16(smb + (so ? OFF_K1 : OFF_K0) + r * RB + ch * 16, src);
            }
            #pragma unroll
            for (int j = 0; j < 2; j++) {
                int c = tid + j * 256;
                int r = c >> 3, ch = c & 7;
                const __half* src = V + (size_t)(b * S_ + (kb + 1) * 64 + r) * 512
                                    + kvh * HD_ + ch * 8;
                CPA16(smb + (so ? OFF_V1 : OFF_V0) + r * RB + ch * 16, src);
            }
            CPA_COMMIT();
            CPA_WAIT1();
        } else {
            CPA_WAIT0();
        }
        __syncthreads();

        // Scores S = Q K^T  (K frags via ldmatrix.x4, 4 per kc)
        float sc[8][4];
        #pragma unroll
        for (int nt = 0; nt < 8; nt++)
            sc[nt][0] = sc[nt][1] = sc[nt][2] = sc[nt][3] = 0.f;
        #pragma unroll
        for (int kc = 0; kc < 4; kc++) {
            #pragma unroll
            for (int np = 0; np < 4; np++) {
                unsigned r0, r1, r2, r3;
                LDSM4(r0, r1, r2, r3, kB + 16 * np * RB + nt_off + 32 * kc);
                MMA_F16(sc[2 * np    ], qfr[kc], r0, r2);
                MMA_F16(sc[2 * np + 1], qfr[kc], r1, r3);
            }
        }

        // Scale + causal mask
        const int kbase = kb * 64;
        #pragma unroll
        for (int nt = 0; nt < 8; nt++) {
            int key0 = kbase + nt * 8 + 2 * tg;
            sc[nt][0] = (key0     > qg0) ? -1e30f : sc[nt][0] * scale;
            sc[nt][1] = (key0 + 1 > qg0) ? -1e30f : sc[nt][1] * scale;
            sc[nt][2] = (key0     > qg1) ? -1e30f : sc[nt][2] * scale;
            sc[nt][3] = (key0 + 1 > qg1) ? -1e30f : sc[nt][3] * scale;
        }

        // Row max
        float mx0 = -1e30f, mx1 = -1e30f;
        #pragma unroll
        for (int nt = 0; nt < 8; nt++) {
            mx0 = fmaxf(mx0, fmaxf(sc[nt][0], sc[nt][1]));
            mx1 = fmaxf(mx1, fmaxf(sc[nt][2], sc[nt][3]));
        }
        mx0 = fmaxf(mx0, __shfl_xor_sync(0xffffffffu, mx0, 1));
        mx0 = fmaxf(mx0, __shfl_xor_sync(0xffffffffu, mx0, 2));
        mx1 = fmaxf(mx1, __shfl_xor_sync(0xffffffffu, mx1, 1));
        mx1 = fmaxf(mx1, __shfl_xor_sync(0xffffffffu, mx1, 2));

        float mn0 = fmaxf(m0, mx0), mn1 = fmaxf(m1, mx1);
        float cr0 = __expf(m0 - mn0), cr1 = __expf(m1 - mn1);
        l0 *= cr0; l1 *= cr1;
        #pragma unroll
        for (int nt = 0; nt < 8; nt++) {
            oacc[nt][0] *= cr0; oacc[nt][1] *= cr0;
            oacc[nt][2] *= cr1; oacc[nt][3] *= cr1;
        }
        m0 = mn0; m1 = mn1;

        // P = exp(S - m) in place, then PV (V frags via ldmatrix.x4.trans)
        #pragma unroll
        for (int nt = 0; nt < 8; nt++) {
            sc[nt][0] = __expf(sc[nt][0] - m0);
            sc[nt][1] = __expf(sc[nt][1] - m0);
            sc[nt][2] = __expf(sc[nt][2] - m1);
            sc[nt][3] = __expf(sc[nt][3] - m1);
            l0 += sc[nt][0] + sc[nt][1];
            l1 += sc[nt][2] + sc[nt][3];
        }
        #pragma unroll
        for (int kc = 0; kc < 4; kc++) {
            unsigned afr[4];
            afr[0] = packh2(sc[2 * kc    ][0], sc[2 * kc    ][1]);
            afr[1] = packh2(sc[2 * kc    ][2], sc[2 * kc    ][3]);
            afr[2] = packh2(sc[2 * kc + 1][0], sc[2 * kc + 1][1]);
            afr[3] = packh2(sc[2 * kc + 1][2], sc[2 * kc + 1][3]);
            #pragma unroll
            for (int np = 0; np < 4; np++) {
                unsigned r0, r1, r2, r3;
                LDSM4T(r0, r1, r2, r3, vB + 16 * kc * RB + tr_off + 32 * np);
                MMA_F16(oacc[2 * np    ], afr, r0, r2);
                MMA_F16(oacc[2 * np + 1], afr, r1, r3);
            }
        }
        __syncthreads();   // all warps done with K/V buffers before restage
    }

    l0 += __shfl_xor_sync(0xffffffffu, l0, 1);
    l0 += __shfl_xor_sync(0xffffffffu, l0, 2);
    l1 += __shfl_xor_sync(0xffffffffu, l1, 1);
    l1 += __shfl_xor_sync(0xffffffffu, l1, 2);
    float inv0 = 1.f / l0, inv1 = 1.f / l1;

    const size_t tok0 = (size_t)(b * S_ + qb * 64 + qrow0 + g);
    const size_t tok1 = tok0 + 8;
    #pragma unroll
    for (int nt = 0; nt < 8; nt++) {
        int col = head * HD_ + nt * 8 + 2 * tg;
        *(unsigned*)(O + tok0 * HID_ + col) =
            packh2(oacc[nt][0] * inv0, oacc[nt][1] * inv0);
        *(unsigned*)(O + tok1 * HID_ + col) =
            packh2(oacc[nt][2] * inv1, oacc[nt][3] * inv1);
    }
}

// ---------------------------------------------------------------------------
// Launch
// ---------------------------------------------------------------------------
extern "C" void kernel_launch(void* const* d_in, const int* in_sizes, int n_in,
                              void* d_out, int out_size)
{
    const float* hid  = (const float*)d_in[0];
    const float* cosT = (const float*)d_in[1];
    const float* sinT = (const float*)d_in[2];
    const float* Wq   = (const float*)d_in[3];
    const float* Wk   = (const float*)d_in[4];
    const float* Wv   = (const float*)d_in[5];
    const float* Wo   = (const float*)d_in[6];
    float* out = (float*)d_out;

    __half *q_p, *k_p, *v_p, *attn_p, *rh_p, *wq_p, *wk_p, *wv_p, *wo_p;
    cudaGetSymbolAddress((void**)&q_p,    g_q);
    cudaGetSymbolAddress((void**)&k_p,    g_k);
    cudaGetSymbolAddress((void**)&v_p,    g_v);
    cudaGetSymbolAddress((void**)&attn_p, g_attn);
    cudaGetSymbolAddress((void**)&rh_p,   g_rh);
    cudaGetSymbolAddress((void**)&wq_p,   g_wq);
    cudaGetSymbolAddress((void**)&wk_p,   g_wk);
    cudaGetSymbolAddress((void**)&wv_p,   g_wv);
    cudaGetSymbolAddress((void**)&wo_p,   g_wo);

    cudaFuncSetAttribute(attn_f16,
                         cudaFuncAttributeMaxDynamicSharedMemorySize, ATT_SMEM);
    cudaFuncSetAttribute(gemm_f16,
                         cudaFuncAttributeMaxDynamicSharedMemorySize, GEMM_SMEM);

    // Convert to fp16 (single elementwise launch)
    convert_all_kernel<<<(CSEG4 + 255) / 256, 256>>>(hid, Wq, Wk, Wv, Wo);

    // Fused QKV projection
    {
        dim3 g(24, 16);
        gemm_f16<<<g, 128, GEMM_SMEM>>>(rh_p, wq_p, wk_p, wv_p,
                                        q_p, k_p, v_p, (float*)0, 0);
    }

    // RoPE (half in place)
    {
        int totq = MTOK * HQ_ * 32;
        rope_kernel<<<(totq + 255) / 256, 256>>>(q_p, cosT, sinT, HQ_);
        int totk = MTOK * HKV_ * 32;
        rope_kernel<<<(totk + 255) / 256, 256>>>(k_p, cosT, sinT, HKV_);
    }

    // Attention
    {
        dim3 ga(S_ / 64, HQ_ / 2, B_);
        attn_f16<<<ga, 256, ATT_SMEM>>>(q_p, k_p, v_p, attn_p);
    }

    // Output projection (fp16 in, fp32 out)
    {
        dim3 go(16, 16);
        gemm_f16<<<go, 128, GEMM_SMEM>>>(attn_p, wo_p, wo_p, wo_p,
                                         (__half*)0, (__half*)0, (__half*)0, out, 1);
    }
}